// round 5
// baseline (speedup 1.0000x reference)
#include <cuda_runtime.h>
#include <cuda_bf16.h>

#define MAX_NODES 500000
#define MAX_EDGES 8000000
#define MAX_GRAPHS 8192
#define FDIM 16
#define SCAN_BS 1024
#define MAX_SCAN_BLOCKS 1024

__device__ int   g_cnt_i[MAX_NODES];            // in-degree (zeroed by memset)
__device__ int   g_off[MAX_NODES];              // block-local exclusive prefix
__device__ int   g_part[MAX_SCAN_BLOCKS];       // exclusive block offsets
__device__ int   g_rank[MAX_EDGES];             // edge rank within its target
__device__ int   g_srcs[MAX_EDGES];             // CSR sources grouped by target
__device__ float g_h[MAX_NODES * FDIM];         // layer1 h * dinv (prescaled)
__device__ float g_h2[MAX_NODES * FDIM];        // layer2 h * dinv (prescaled)
__device__ float g_pool[MAX_GRAPHS * FDIM];
__device__ float g_gcnt[MAX_GRAPHS];

__device__ __forceinline__ void red_v4(float* addr, float4 v) {
    asm volatile("red.global.add.v4.f32 [%0], {%1,%2,%3,%4};"
                 :: "l"(addr), "f"(v.x), "f"(v.y), "f"(v.z), "f"(v.w)
                 : "memory");
}

// 1) count in-degree AND record each edge's rank within its target
__global__ void k_count(const int* __restrict__ cols, int E) {
    int e = blockIdx.x * blockDim.x + threadIdx.x;
    if (e < E) g_rank[e] = atomicAdd(&g_cnt_i[cols[e]], 1);
}

// 2) block-level exclusive scan, emit block totals
__global__ void k_scan1(int N) {
    __shared__ int sm[SCAN_BS];
    int tid = threadIdx.x;
    int i = blockIdx.x * SCAN_BS + tid;
    int v = (i < N) ? g_cnt_i[i] : 0;
    sm[tid] = v;
    __syncthreads();
    for (int off = 1; off < SCAN_BS; off <<= 1) {
        int t = (tid >= off) ? sm[tid - off] : 0;
        __syncthreads();
        sm[tid] += t;
        __syncthreads();
    }
    if (i < N) g_off[i] = sm[tid] - v;
    if (tid == SCAN_BS - 1) g_part[blockIdx.x] = sm[tid];
}

// 3) exclusive scan of block totals in place (NB <= 1024)
__global__ void k_scan2(int NB) {
    __shared__ int sm[SCAN_BS];
    int tid = threadIdx.x;
    int v = (tid < NB) ? g_part[tid] : 0;
    sm[tid] = v;
    __syncthreads();
    for (int off = 1; off < SCAN_BS; off <<= 1) {
        int t = (tid >= off) ? sm[tid - off] : 0;
        __syncthreads();
        sm[tid] += t;
        __syncthreads();
    }
    if (tid < NB) g_part[tid] = sm[tid] - v;
}

// 4) fill CSR — NO atomics: slot = offset(c) + rank(e)
__global__ void k_fill(const int* __restrict__ rows, const int* __restrict__ cols,
                       int E) {
    int e = blockIdx.x * blockDim.x + threadIdx.x;
    if (e >= E) return;
    int c = cols[e];
    int p = g_off[c] + g_part[c >> 10] + g_rank[e];
    g_srcs[p] = rows[e];
}

// 5) layer1 dense: g_h = (x @ W1) * dinv, dinv computed on the fly
__global__ void k_layer1(const float* __restrict__ x, const float* __restrict__ W1,
                         int N) {
    __shared__ float sx[128 * 9];
    int base = blockIdx.x * 128;
    int n = base + threadIdx.x;
    int lim = min(128, N - base) * 9;
    for (int i = threadIdx.x; i < lim; i += 128)
        sx[i] = x[(long long)base * 9 + i];
    __syncthreads();
    if (n >= N) return;
    float xi[9];
#pragma unroll
    for (int k = 0; k < 9; k++) xi[k] = sx[threadIdx.x * 9 + k];
    float di = rsqrtf((float)g_cnt_i[n] + 1.0f);
    float4* hp = (float4*)&g_h[n * FDIM];
#pragma unroll
    for (int q = 0; q < 4; q++) {
        float s[4];
#pragma unroll
        for (int j = 0; j < 4; j++) {
            float acc = 0.0f;
#pragma unroll
            for (int k = 0; k < 9; k++) acc += xi[k] * __ldg(&W1[k * FDIM + q * 4 + j]);
            s[j] = acc * di;
        }
        hp[q] = make_float4(s[0], s[1], s[2], s[3]);
    }
}

// 6/7) CSR gather, one warp per node (8 edge-slots x 4 feature-quarters).
// PASS 0: epilogue = relu(+b1) then 16x16 matmul (shfl), store g_h2 prescaled.
// PASS 1: epilogue = relu(+b2), red.v4 into pool, gcnt count.
template <int PASS>
__global__ void k_gather(const int* __restrict__ batch,
                         const float* __restrict__ bias,
                         const float* __restrict__ W2, int N, int E) {
    int warp = (blockIdx.x * blockDim.x + threadIdx.x) >> 5;
    if (warp >= N) return;
    int lane = threadIdx.x & 31;
    int q = lane & 3, slot = lane >> 2;
    const float* H = (PASS == 0) ? g_h : g_h2;
    int s0 = g_off[warp] + g_part[warp >> 10];
    int s1 = (warp + 1 < N) ? (g_off[warp + 1] + g_part[(warp + 1) >> 10]) : E;
    float4 acc;
    if (slot == 0) acc = *(const float4*)&H[warp * FDIM + q * 4];  // self-loop
    else           acc = make_float4(0.f, 0.f, 0.f, 0.f);
    for (int e = s0 + slot; e < s1; e += 8) {
        int r = __ldg(&g_srcs[e]);
        float4 hv = *(const float4*)&H[r * FDIM + q * 4];
        acc.x += hv.x; acc.y += hv.y; acc.z += hv.z; acc.w += hv.w;
    }
#pragma unroll
    for (int m = 4; m <= 16; m <<= 1) {
        acc.x += __shfl_xor_sync(0xffffffffu, acc.x, m);
        acc.y += __shfl_xor_sync(0xffffffffu, acc.y, m);
        acc.z += __shfl_xor_sync(0xffffffffu, acc.z, m);
        acc.w += __shfl_xor_sync(0xffffffffu, acc.w, m);
    }
    float di = rsqrtf((float)(s1 - s0) + 1.0f);
    float4 a;  // relu(agg*dinv + bias) — this lane's feature quarter q
    a.x = fmaxf(acc.x * di + __ldg(&bias[q * 4 + 0]), 0.0f);
    a.y = fmaxf(acc.y * di + __ldg(&bias[q * 4 + 1]), 0.0f);
    a.z = fmaxf(acc.z * di + __ldg(&bias[q * 4 + 2]), 0.0f);
    a.w = fmaxf(acc.w * di + __ldg(&bias[q * 4 + 3]), 0.0f);

    if (PASS == 0) {
        // 16x16 matmul across the quad: out[4q+j] = sum_k a[k] * W2[k][4q+j]
        float4 o = make_float4(0.f, 0.f, 0.f, 0.f);
        int base = lane & ~3;
#pragma unroll
        for (int kk = 0; kk < 4; kk++) {
            float4 ak;
            ak.x = __shfl_sync(0xffffffffu, a.x, base + kk);
            ak.y = __shfl_sync(0xffffffffu, a.y, base + kk);
            ak.z = __shfl_sync(0xffffffffu, a.z, base + kk);
            ak.w = __shfl_sync(0xffffffffu, a.w, base + kk);
            const float* Wr = &W2[(kk * 4) * FDIM + q * 4];
#pragma unroll
            for (int j = 0; j < 4; j++) {
                float* oj = (&o.x) + j;
                *oj += ak.x * __ldg(Wr + 0 * FDIM + j)
                     + ak.y * __ldg(Wr + 1 * FDIM + j)
                     + ak.z * __ldg(Wr + 2 * FDIM + j)
                     + ak.w * __ldg(Wr + 3 * FDIM + j);
            }
        }
        if (slot == 0) {
            o.x *= di; o.y *= di; o.z *= di; o.w *= di;
            *(float4*)&g_h2[warp * FDIM + q * 4] = o;
        }
    } else {
        int g = __ldg(&batch[warp]);
        if (slot == 0) red_v4(&g_pool[g * FDIM + q * 4], a);
        else if (slot == 1 && q == 0) atomicAdd(&g_gcnt[g], 1.0f);
    }
}

// 8) MLP head
__global__ void k_mlp(const float* __restrict__ meta,
                      const float* __restrict__ Wh1, const float* __restrict__ bh1,
                      const float* __restrict__ Wh2, const float* __restrict__ bh2,
                      float* __restrict__ out, int G) {
    int g = blockIdx.x * blockDim.x + threadIdx.x;
    if (g >= G) return;
    float inv = 1.0f / fmaxf(g_gcnt[g], 1.0f);
    float z[FDIM];
#pragma unroll
    for (int f = 0; f < FDIM; f++) z[f] = __ldg(&bh1[f]);
#pragma unroll
    for (int k = 0; k < FDIM; k++) {
        float e = g_pool[g * FDIM + k] * inv;
#pragma unroll
        for (int f = 0; f < FDIM; f++) z[f] += e * __ldg(&Wh1[k * FDIM + f]);
    }
    for (int k = 0; k < 27; k++) {
        float m = meta[g * 27 + k];
#pragma unroll
        for (int f = 0; f < FDIM; f++) z[f] += m * __ldg(&Wh1[(FDIM + k) * FDIM + f]);
    }
    float o = __ldg(&bh2[0]);
#pragma unroll
    for (int f = 0; f < FDIM; f++) o += fmaxf(z[f], 0.0f) * __ldg(&Wh2[f]);
    out[g] = o;
}

extern "C" void kernel_launch(void* const* d_in, const int* in_sizes, int n_in,
                              void* d_out, int out_size) {
    const float* x    = (const float*)d_in[0];
    const int*   ei   = (const int*)d_in[1];
    const int*   batch= (const int*)d_in[2];
    const float* meta = (const float*)d_in[3];
    const float* W1   = (const float*)d_in[4];
    const float* b1   = (const float*)d_in[5];
    const float* W2   = (const float*)d_in[6];
    const float* b2   = (const float*)d_in[7];
    const float* Wh1  = (const float*)d_in[8];
    const float* bh1  = (const float*)d_in[9];
    const float* Wh2  = (const float*)d_in[10];
    const float* bh2  = (const float*)d_in[11];
    float* out = (float*)d_out;

    const int N = in_sizes[0] / 9;
    const int E = in_sizes[1] / 2;
    const int G = in_sizes[3] / 27;
    const int* rows = ei;      // source
    const int* cols = ei + E;  // target

    const int B = 256;
    const int NB_SCAN = (N + SCAN_BS - 1) / SCAN_BS;

    // zeroing via memset nodes (not kernels)
    void *p_cnt, *p_pool, *p_gcnt;
    cudaGetSymbolAddress(&p_cnt, g_cnt_i);
    cudaGetSymbolAddress(&p_pool, g_pool);
    cudaGetSymbolAddress(&p_gcnt, g_gcnt);
    cudaMemsetAsync(p_cnt, 0, (size_t)N * sizeof(int));
    cudaMemsetAsync(p_pool, 0, (size_t)G * FDIM * sizeof(float));
    cudaMemsetAsync(p_gcnt, 0, (size_t)G * sizeof(float));

    k_count<<<(E + B - 1) / B, B>>>(cols, E);
    k_scan1<<<NB_SCAN, SCAN_BS>>>(N);
    k_scan2<<<1, SCAN_BS>>>(NB_SCAN);
    k_fill<<<(E + B - 1) / B, B>>>(rows, cols, E);
    k_layer1<<<(N + 127) / 128, 128>>>(x, W1, N);
    {
        long long t = (long long)N * 32;
        int nb = (int)((t + B - 1) / B);
        k_gather<0><<<nb, B>>>(batch, b1, W2, N, E);
        k_gather<1><<<nb, B>>>(batch, b2, W2, N, E);
    }
    k_mlp<<<(G + B - 1) / B, B>>>(meta, Wh1, bh1, Wh2, bh2, out, G);
}

// round 6
// speedup vs baseline: 1.2219x; 1.2219x over previous
#include <cuda_runtime.h>
#include <cuda_fp16.h>

#define MAX_NODES 500000
#define MAX_EDGES 8000000
#define MAX_GRAPHS 8192
#define FDIM 16
#define SCAN_BS 1024
#define MAX_SCAN_BLOCKS 1024

__device__ int    g_cnt_i[MAX_NODES];            // in-degree (memset to 0)
__device__ int    g_off[MAX_NODES + 1];          // CSR offsets (absolute)
__device__ int    g_cursor[MAX_NODES];           // fill cursors
__device__ int    g_part[MAX_SCAN_BLOCKS];
__device__ int    g_srcs[MAX_EDGES];             // CSR sources grouped by target
__device__ __half g_h[MAX_NODES * FDIM];         // layer1 h*dinv, fp16 (16MB)
__device__ __half g_h2[MAX_NODES * FDIM];        // layer2 h*dinv, fp16
__device__ float  g_agg[MAX_NODES * FDIM];       // gather0 output (fp32 sums)
__device__ float  g_pool[MAX_GRAPHS * FDIM];
__device__ float  g_gcnt[MAX_GRAPHS];

__device__ __forceinline__ void red_v4(float* addr, float4 v) {
    asm volatile("red.global.add.v4.f32 [%0], {%1,%2,%3,%4};"
                 :: "l"(addr), "f"(v.x), "f"(v.y), "f"(v.z), "f"(v.w)
                 : "memory");
}

// pack 16 fp32 (scaled by di) -> 32B of fp16 at dst
__device__ __forceinline__ void store_h16(__half* dst, const float* s, float di) {
    __align__(16) __half2 hh[8];
#pragma unroll
    for (int q = 0; q < 8; q++)
        hh[q] = __floats2half2_rn(s[2 * q] * di, s[2 * q + 1] * di);
    *(uint4*)dst       = *(uint4*)&hh[0];
    *(uint4*)(dst + 8) = *(uint4*)&hh[4];
}

// 1) in-degree count
__global__ void k_count(const int* __restrict__ cols, int E) {
    int e = blockIdx.x * blockDim.x + threadIdx.x;
    if (e < E) atomicAdd(&g_cnt_i[cols[e]], 1);
}

// 2) block-level exclusive scan
__global__ void k_scan1(int N) {
    __shared__ int sm[SCAN_BS];
    int tid = threadIdx.x;
    int i = blockIdx.x * SCAN_BS + tid;
    int v = (i < N) ? g_cnt_i[i] : 0;
    sm[tid] = v;
    __syncthreads();
    for (int off = 1; off < SCAN_BS; off <<= 1) {
        int t = (tid >= off) ? sm[tid - off] : 0;
        __syncthreads();
        sm[tid] += t;
        __syncthreads();
    }
    if (i < N) g_off[i] = sm[tid] - v;
    if (tid == SCAN_BS - 1) g_part[blockIdx.x] = sm[tid];
}

// 3) scan of block totals
__global__ void k_scan2(int NB) {
    __shared__ int sm[SCAN_BS];
    int tid = threadIdx.x;
    int v = (tid < NB) ? g_part[tid] : 0;
    sm[tid] = v;
    __syncthreads();
    for (int off = 1; off < SCAN_BS; off <<= 1) {
        int t = (tid >= off) ? sm[tid - off] : 0;
        __syncthreads();
        sm[tid] += t;
        __syncthreads();
    }
    if (tid < NB) g_part[tid] = sm[tid] - v;
}

// 4) finalize absolute offsets + cursors
__global__ void k_scan3(int N, int E) {
    int i = blockIdx.x * blockDim.x + threadIdx.x;
    if (i < N) {
        int v = g_off[i] + g_part[i >> 10];
        g_off[i] = v;
        g_cursor[i] = v;
    }
    if (i == 0) g_off[N] = E;
}

// 5) fill via atomic cursor
__global__ void k_fill(const int* __restrict__ rows, const int* __restrict__ cols,
                       int E) {
    int e = blockIdx.x * blockDim.x + threadIdx.x;
    if (e >= E) return;
    int p = atomicAdd(&g_cursor[cols[e]], 1);
    g_srcs[p] = rows[e];
}

// 6) layer1 dense: g_h = fp16((x @ W1) * dinv)
__global__ void k_layer1(const float* __restrict__ x, const float* __restrict__ W1,
                         int N) {
    __shared__ float sx[128 * 9];
    int base = blockIdx.x * 128;
    int n = base + threadIdx.x;
    int lim = min(128, N - base) * 9;
    for (int i = threadIdx.x; i < lim; i += 128)
        sx[i] = x[(long long)base * 9 + i];
    __syncthreads();
    if (n >= N) return;
    float xi[9];
#pragma unroll
    for (int k = 0; k < 9; k++) xi[k] = sx[threadIdx.x * 9 + k];
    float di = rsqrtf((float)g_cnt_i[n] + 1.0f);
    float s[FDIM];
#pragma unroll
    for (int f = 0; f < FDIM; f++) {
        float acc = 0.0f;
#pragma unroll
        for (int k = 0; k < 9; k++) acc += xi[k] * __ldg(&W1[k * FDIM + f]);
        s[f] = acc;
    }
    store_h16(&g_h[n * FDIM], s, di);
}

// 7/9) CSR gather, one warp/node; quad per edge, each lane loads 8B (4 halves).
// PASS 0: write raw fp32 sums to g_agg.
// PASS 1: epilogue relu(acc*di + b2) -> red.v4 pool + gcnt.
template <int PASS>
__global__ void k_gather(const int* __restrict__ batch,
                         const float* __restrict__ b2, int N) {
    int warp = (blockIdx.x * blockDim.x + threadIdx.x) >> 5;
    if (warp >= N) return;
    int lane = threadIdx.x & 31;
    int q = lane & 3, slot = lane >> 2;
    const __half* H = (PASS == 0) ? g_h : g_h2;
    int s0 = __ldg(&g_off[warp]), s1 = __ldg(&g_off[warp + 1]);
    float4 acc = make_float4(0.f, 0.f, 0.f, 0.f);
    int e0 = (slot == 0) ? s0 - 1 : s0 + slot - 1;  // slot0 handles self-loop first
    for (int e = e0; e < s1; e += 8) {
        int r = (e < s0) ? warp : __ldg(&g_srcs[e]);
        uint2 u = *(const uint2*)&H[r * FDIM + q * 4];
        float2 f0 = __half22float2(*(__half2*)&u.x);
        float2 f1 = __half22float2(*(__half2*)&u.y);
        acc.x += f0.x; acc.y += f0.y; acc.z += f1.x; acc.w += f1.y;
    }
#pragma unroll
    for (int m = 4; m <= 16; m <<= 1) {
        acc.x += __shfl_xor_sync(0xffffffffu, acc.x, m);
        acc.y += __shfl_xor_sync(0xffffffffu, acc.y, m);
        acc.z += __shfl_xor_sync(0xffffffffu, acc.z, m);
        acc.w += __shfl_xor_sync(0xffffffffu, acc.w, m);
    }
    if (PASS == 0) {
        if (slot == 0) *(float4*)&g_agg[warp * FDIM + q * 4] = acc;
    } else {
        float di = rsqrtf((float)(s1 - s0) + 1.0f);
        if (slot == 0) {
            float4 a;
            a.x = fmaxf(acc.x * di + __ldg(&b2[q * 4 + 0]), 0.0f);
            a.y = fmaxf(acc.y * di + __ldg(&b2[q * 4 + 1]), 0.0f);
            a.z = fmaxf(acc.z * di + __ldg(&b2[q * 4 + 2]), 0.0f);
            a.w = fmaxf(acc.w * di + __ldg(&b2[q * 4 + 3]), 0.0f);
            red_v4(&g_pool[__ldg(&batch[warp]) * FDIM + q * 4], a);
        } else if (slot == 1 && q == 0) {
            atomicAdd(&g_gcnt[__ldg(&batch[warp])], 1.0f);
        }
    }
}

// 8) transform: a = relu(agg*di + b1); g_h2 = fp16((a @ W2) * di); W2 in smem
__global__ void k_transform(const float* __restrict__ b1, const float* __restrict__ W2,
                            int N) {
    __shared__ float sW[FDIM * FDIM];
    if (threadIdx.x < FDIM * FDIM) sW[threadIdx.x] = W2[threadIdx.x];
    __syncthreads();
    int n = blockIdx.x * blockDim.x + threadIdx.x;
    if (n >= N) return;
    float di = rsqrtf((float)g_cnt_i[n] + 1.0f);
    float a[FDIM];
    const float4* ain = (const float4*)&g_agg[n * FDIM];
#pragma unroll
    for (int qq = 0; qq < 4; qq++) {
        float4 v = ain[qq];
        a[qq*4+0] = fmaxf(v.x * di + __ldg(&b1[qq*4+0]), 0.0f);
        a[qq*4+1] = fmaxf(v.y * di + __ldg(&b1[qq*4+1]), 0.0f);
        a[qq*4+2] = fmaxf(v.z * di + __ldg(&b1[qq*4+2]), 0.0f);
        a[qq*4+3] = fmaxf(v.w * di + __ldg(&b1[qq*4+3]), 0.0f);
    }
    float s[FDIM];
#pragma unroll
    for (int f = 0; f < FDIM; f++) {
        float acc = 0.0f;
#pragma unroll
        for (int k = 0; k < FDIM; k++) acc += a[k] * sW[k * FDIM + f];
        s[f] = acc;
    }
    store_h16(&g_h2[n * FDIM], s, di);
}

// 10) MLP head
__global__ void k_mlp(const float* __restrict__ meta,
                      const float* __restrict__ Wh1, const float* __restrict__ bh1,
                      const float* __restrict__ Wh2, const float* __restrict__ bh2,
                      float* __restrict__ out, int G) {
    int g = blockIdx.x * blockDim.x + threadIdx.x;
    if (g >= G) return;
    float inv = 1.0f / fmaxf(g_gcnt[g], 1.0f);
    float z[FDIM];
#pragma unroll
    for (int f = 0; f < FDIM; f++) z[f] = __ldg(&bh1[f]);
#pragma unroll
    for (int k = 0; k < FDIM; k++) {
        float e = g_pool[g * FDIM + k] * inv;
#pragma unroll
        for (int f = 0; f < FDIM; f++) z[f] += e * __ldg(&Wh1[k * FDIM + f]);
    }
    for (int k = 0; k < 27; k++) {
        float m = meta[g * 27 + k];
#pragma unroll
        for (int f = 0; f < FDIM; f++) z[f] += m * __ldg(&Wh1[(FDIM + k) * FDIM + f]);
    }
    float o = __ldg(&bh2[0]);
#pragma unroll
    for (int f = 0; f < FDIM; f++) o += fmaxf(z[f], 0.0f) * __ldg(&Wh2[f]);
    out[g] = o;
}

extern "C" void kernel_launch(void* const* d_in, const int* in_sizes, int n_in,
                              void* d_out, int out_size) {
    const float* x    = (const float*)d_in[0];
    const int*   ei   = (const int*)d_in[1];
    const int*   batch= (const int*)d_in[2];
    const float* meta = (const float*)d_in[3];
    const float* W1   = (const float*)d_in[4];
    const float* b1   = (const float*)d_in[5];
    const float* W2   = (const float*)d_in[6];
    const float* b2   = (const float*)d_in[7];
    const float* Wh1  = (const float*)d_in[8];
    const float* bh1  = (const float*)d_in[9];
    const float* Wh2  = (const float*)d_in[10];
    const float* bh2  = (const float*)d_in[11];
    float* out = (float*)d_out;

    const int N = in_sizes[0] / 9;
    const int E = in_sizes[1] / 2;
    const int G = in_sizes[3] / 27;
    const int* rows = ei;      // source
    const int* cols = ei + E;  // target

    const int B = 256;
    const int NB_SCAN = (N + SCAN_BS - 1) / SCAN_BS;

    void *p_cnt, *p_pool, *p_gcnt;
    cudaGetSymbolAddress(&p_cnt, g_cnt_i);
    cudaGetSymbolAddress(&p_pool, g_pool);
    cudaGetSymbolAddress(&p_gcnt, g_gcnt);
    cudaMemsetAsync(p_cnt, 0, (size_t)N * sizeof(int));
    cudaMemsetAsync(p_pool, 0, (size_t)G * FDIM * sizeof(float));
    cudaMemsetAsync(p_gcnt, 0, (size_t)G * sizeof(float));

    k_count<<<(E + B - 1) / B, B>>>(cols, E);
    k_scan1<<<NB_SCAN, SCAN_BS>>>(N);
    k_scan2<<<1, SCAN_BS>>>(NB_SCAN);
    k_scan3<<<(N + B - 1) / B, B>>>(N, E);
    k_fill<<<(E + B - 1) / B, B>>>(rows, cols, E);
    k_layer1<<<(N + 127) / 128, 128>>>(x, W1, N);
    {
        long long t = (long long)N * 32;
        int nb = (int)((t + B - 1) / B);
        k_gather<0><<<nb, B>>>(batch, b2, N);
        k_transform<<<(N + B - 1) / B, B>>>(b1, W2, N);
        k_gather<1><<<nb, B>>>(batch, b2, N);
    }
    k_mlp<<<(G + B - 1) / B, B>>>(meta, Wh1, bh1, Wh2, bh2, out, G);
}